// round 2
// baseline (speedup 1.0000x reference)
#include <cuda_runtime.h>

#define BB 4
#define TT 1024
#define CHN 4
#define FF 481
#define KK 48
#define NC 16

// scratch: band-cov intermediate, (b,t,k,c) complex — scanned in place
__device__ float2 g_bc[BB * TT * KK * NC];  // 25.2 MB

__device__ __forceinline__ unsigned long long fma2(unsigned long long a,
                                                   unsigned long long b,
                                                   unsigned long long c) {
    unsigned long long d;
    asm("fma.rn.f32x2 %0, %1, %2, %3;" : "=l"(d) : "l"(a), "l"(b), "l"(c));
    return d;
}
__device__ __forceinline__ unsigned long long pack2(float lo, float hi) {
    unsigned long long r;
    asm("mov.b64 %0, {%1, %2};" : "=l"(r) : "f"(lo), "f"(hi));
    return r;
}
__device__ __forceinline__ void unpack2(unsigned long long v, float& lo, float& hi) {
    asm("mov.b64 {%0, %1}, %2;" : "=f"(lo), "=f"(hi) : "l"(v));
}
__device__ __forceinline__ unsigned long long lds64(unsigned addr) {
    unsigned long long v;
    asm volatile("ld.shared.b64 %0, [%1];" : "=l"(v) : "r"(addr));
    return v;
}

// ---------------------------------------------------------------------------
// Kernel 1: per (b,t): cov -> phase-adjust -> band GEMM -> diag-normalize
// ---------------------------------------------------------------------------
__global__ void __launch_bounds__(256, 1) band_cov_kernel(
    const float* __restrict__ binr, const float* __restrict__ bini,
    const float* __restrict__ bandr, const float* __restrict__ bandi) {
    extern __shared__ float sm[];
    float* s_xr = sm;                       // CHN*FF
    float* s_xi = s_xr + CHN * FF;          // CHN*FF
    float* s_cx = s_xi + CHN * FF;          // FF*NC
    float* s_cy = s_cx + FF * NC;           // FF*NC
    float* s_ax = s_cy + FF * NC;           // FF*NC
    float* s_ay = s_ax + FF * NC;           // FF*NC

    const int bt = blockIdx.x;
    const int tid = threadIdx.x;

    // --- phase 1: load x tile ---
    {
        const float* br_ = binr + (size_t)bt * CHN * FF;
        const float* bi_ = bini + (size_t)bt * CHN * FF;
        for (int i = tid; i < CHN * FF; i += 256) {
            s_xr[i] = br_[i];
            s_xi[i] = bi_[i];
        }
    }
    __syncthreads();

    // --- phase 2: normalized covariance per bin ---
    for (int f = tid; f < FF; f += 256) {
        float xr[CHN], xi[CHN];
        float pw = 0.f;
#pragma unroll
        for (int c = 0; c < CHN; c++) {
            xr[c] = s_xr[c * FF + f];
            xi[c] = s_xi[c * FF + f];
            pw += xr[c] * xr[c] + xi[c] * xi[c];
        }
        float inv = 1.0f / fmaxf(pw, 1e-20f);
#pragma unroll
        for (int i = 0; i < CHN; i++)
#pragma unroll
            for (int j = 0; j < CHN; j++) {
                int c = i * 4 + j;
                // x_i * conj(x_j)
                s_cx[f * NC + c] = (xr[i] * xr[j] + xi[i] * xi[j]) * inv;
                s_cy[f * NC + c] = (xi[i] * xr[j] - xr[i] * xi[j]) * inv;
            }
    }
    __syncthreads();

    // --- phase 3: phase adjustment: adj = |cov_f| * z/|z|, z = conj(cov_fm)*cov_fp ---
    for (int f = tid; f < FF; f += 256) {
        int fm = (f == 0) ? 0 : ((f == FF - 1) ? FF - 3 : f - 1);
        int fp = (f == 0) ? 2 : ((f == FF - 1) ? FF - 1 : f + 1);
#pragma unroll
        for (int c = 0; c < NC; c++) {
            float cx = s_cx[f * NC + c], cy = s_cy[f * NC + c];
            float ax, ay;
            if (c == 0 || c == 5 || c == 10 || c == 15) {
                ax = cx;
                ay = cy;  // exactly 0 for diag
            } else {
                float a = s_cx[fm * NC + c], b = s_cy[fm * NC + c];
                float cc = s_cx[fp * NC + c], d = s_cy[fp * NC + c];
                float zr = a * cc + b * d;   // Re(conj(u)v)
                float zi = a * d - b * cc;   // Im(conj(u)v)
                float zl2 = zr * zr + zi * zi;
                float m = sqrtf(cx * cx + cy * cy);
                if (zl2 > 0.f) {
                    float s = m * rsqrtf(zl2);
                    ax = s * zr;
                    ay = s * zi;
                } else {
                    ax = m;  // angle(0)=0 -> exp(i0)=1
                    ay = 0.f;
                }
            }
            s_ax[f * NC + c] = ax;
            s_ay[f * NC + c] = ay;
        }
    }
    __syncthreads();

    // --- phase 4: bc[k][c] = sum_f adj[f][c] * band[f][k]  (FFMA2 inner loop) ---
    const int NFG = 5;
    const int CHUNK = (FF + NFG - 1) / NFG;  // 97
    unsigned long long accX[8], accY[8];
#pragma unroll
    for (int p = 0; p < 8; p++) {
        accX[p] = 0ull;
        accY[p] = 0ull;
    }
    if (tid < NFG * KK) {
        const int fg = tid / KK, k = tid % KK;
        const int f0 = fg * CHUNK;
        const int f1 = (f0 + CHUNK < FF) ? f0 + CHUNK : FF;
        unsigned axbase = (unsigned)__cvta_generic_to_shared(s_ax);
        unsigned aybase = (unsigned)__cvta_generic_to_shared(s_ay);
        for (int f = f0; f < f1; f++) {
            float brv = bandr[f * KK + k];
            float biv = bandi[f * KK + k];
            unsigned long long brbr = pack2(brv, brv);
            unsigned long long bibi = pack2(biv, biv);
            unsigned long long nbnb = pack2(-biv, -biv);
            unsigned axa = axbase + f * NC * 4;
            unsigned aya = aybase + f * NC * 4;
#pragma unroll
            for (int p = 0; p < 8; p++) {
                unsigned long long AX = lds64(axa + p * 8);
                unsigned long long AY = lds64(aya + p * 8);
                accX[p] = fma2(AX, brbr, accX[p]);
                accX[p] = fma2(AY, nbnb, accX[p]);
                accY[p] = fma2(AX, bibi, accY[p]);
                accY[p] = fma2(AY, brbr, accY[p]);
            }
        }
    }
    __syncthreads();

    // --- partial reduction over the 5 f-chunks (reuse cov planes) ---
    if (tid < NFG * KK) {
        const int fg = tid / KK, k = tid % KK;
        float* px = s_cx + fg * (KK * NC) + k * NC;
        float* py = s_cy + fg * (KK * NC) + k * NC;
#pragma unroll
        for (int p = 0; p < 8; p++) {
            float lo, hi;
            unpack2(accX[p], lo, hi);
            px[2 * p] = lo;
            px[2 * p + 1] = hi;
            unpack2(accY[p], lo, hi);
            py[2 * p] = lo;
            py[2 * p + 1] = hi;
        }
    }
    __syncthreads();

    // sum 5 partials -> bc staged in s_xr/s_xi (768 floats each)
    for (int s = tid; s < KK * NC; s += 256) {
        float sx = 0.f, sy = 0.f;
#pragma unroll
        for (int fg = 0; fg < NFG; fg++) {
            sx += s_cx[fg * (KK * NC) + s];
            sy += s_cy[fg * (KK * NC) + s];
        }
        s_xr[s] = sx;
        s_xi[s] = sy;
    }
    __syncthreads();

    // --- normalize by clipped diagonal sum, write to global ---
    for (int s = tid; s < KK * NC; s += 256) {
        int k = s >> 4;
        float ds = s_xr[k * NC + 0] + s_xr[k * NC + 5] + s_xr[k * NC + 10] +
                   s_xr[k * NC + 15];
        float inv = 1.0f / fmaxf(ds, 1e-20f);
        g_bc[(size_t)bt * (KK * NC) + s] = make_float2(s_xr[s] * inv, s_xi[s] * inv);
    }
}

// ---------------------------------------------------------------------------
// Kernel 2: in-place IIR scan over t per (b,k,c) chain
// ---------------------------------------------------------------------------
__global__ void scan_kernel(const float* __restrict__ tau) {
    int id = blockIdx.x * 256 + threadIdx.x;
    if (id >= BB * KK * NC) return;
    int c = id & 15;
    int k = (id >> 4) % KK;
    int b = id / (KK * NC);

    float a = expf(-10.0f / tau[k]);
    float om = 1.0f - a;

    size_t base = (size_t)b * TT * KK * NC + (size_t)k * NC + c;
    const size_t stride = KK * NC;

    float2 y = g_bc[base];               // t = 0: y_0 = x_0 (left in place)
    float2 x = g_bc[base + stride];      // prefetch t = 1
#pragma unroll 4
    for (int t = 1; t < TT; t++) {
        float2 xn;
        if (t + 1 < TT) xn = g_bc[base + (size_t)(t + 1) * stride];
        y.x = a * y.x + om * x.x;
        y.y = a * y.y + om * x.y;
        g_bc[base + (size_t)t * stride] = y;
        x = xn;
    }
}

// ---------------------------------------------------------------------------
// Kernel 3: pv[b,k,t,p] = Re( c2pv[p,:] . y[b,t,k,:] )
// ---------------------------------------------------------------------------
__global__ void __launch_bounds__(256) proj_kernel(const float* __restrict__ pr,
                                                   const float* __restrict__ pi,
                                                   float* __restrict__ out) {
    __shared__ float cr[256], ci[256];  // transposed: [c][p]
    int tid = threadIdx.x;
    {
        int c = tid >> 4, p = tid & 15;
        cr[c * 16 + p] = pr[p * 16 + c];
        ci[c * 16 + p] = pi[p * 16 + c];
    }
    __syncthreads();

    int g = blockIdx.x * 16 + (tid >> 4);  // flat (b,k,t) in output order
    int p = tid & 15;
    int t = g % TT;
    int bk = g / TT;
    int b = bk / KK, k = bk % KK;

    size_t ybase = (((size_t)b * TT + t) * KK + k) * NC;
    float s = 0.f;
#pragma unroll
    for (int c = 0; c < NC; c++) {
        float2 y = g_bc[ybase + c];
        s = fmaf(cr[c * 16 + p], y.x, s);
        s = fmaf(-ci[c * 16 + p], y.y, s);
    }
    out[(size_t)g * 16 + p] = s;
}

// ---------------------------------------------------------------------------
extern "C" void kernel_launch(void* const* d_in, const int* in_sizes, int n_in,
                              void* d_out, int out_size) {
    const float* binr = (const float*)d_in[0];
    const float* bini = (const float*)d_in[1];
    const float* bandr = (const float*)d_in[2];
    const float* bandi = (const float*)d_in[3];
    const float* pr = (const float*)d_in[4];
    const float* pi = (const float*)d_in[5];
    const float* tau = (const float*)d_in[6];
    float* out = (float*)d_out;

    const int smem = (2 * CHN * FF + 4 * FF * NC) * (int)sizeof(float);  // 138528 B
    cudaFuncSetAttribute(band_cov_kernel,
                         cudaFuncAttributeMaxDynamicSharedMemorySize, smem);

    band_cov_kernel<<<BB * TT, 256, smem>>>(binr, bini, bandr, bandi);
    scan_kernel<<<(BB * KK * NC + 255) / 256, 256>>>(tau);
    proj_kernel<<<BB * KK * TT / 16, 256>>>(pr, pi, out);
}

// round 3
// speedup vs baseline: 1.2728x; 1.2728x over previous
#include <cuda_runtime.h>

#define BB 4
#define TT 1024
#define CHN 4
#define FF 481
#define KK 48
#define NC 16
#define NTHR 512

// scratch: band-cov intermediate, (b,t,k,c) complex — scanned in place
__device__ float2 g_bc[BB * TT * KK * NC];  // 25.2 MB

__device__ __forceinline__ unsigned long long fma2(unsigned long long a,
                                                   unsigned long long b,
                                                   unsigned long long c) {
    unsigned long long d;
    asm("fma.rn.f32x2 %0, %1, %2, %3;" : "=l"(d) : "l"(a), "l"(b), "l"(c));
    return d;
}
__device__ __forceinline__ unsigned long long pack2(float lo, float hi) {
    unsigned long long r;
    asm("mov.b64 %0, {%1, %2};" : "=l"(r) : "f"(lo), "f"(hi));
    return r;
}
__device__ __forceinline__ void unpack2(unsigned long long v, float& lo, float& hi) {
    asm("mov.b64 {%0, %1}, %2;" : "=f"(lo), "=f"(hi) : "l"(v));
}
__device__ __forceinline__ unsigned long long lds64(unsigned addr) {
    unsigned long long v;
    asm volatile("ld.shared.b64 %0, [%1];" : "=l"(v) : "r"(addr));
    return v;
}

// ---------------------------------------------------------------------------
// Kernel 1: per (b,t): cov -> phase-adjust -> band GEMM -> diag-normalize
// ---------------------------------------------------------------------------
__global__ void __launch_bounds__(NTHR, 1) band_cov_kernel(
    const float* __restrict__ binr, const float* __restrict__ bini,
    const float* __restrict__ bandr, const float* __restrict__ bandi) {
    extern __shared__ float sm[];
    float* s_xr = sm;                       // CHN*FF
    float* s_xi = s_xr + CHN * FF;          // CHN*FF
    float* s_cx = s_xi + CHN * FF;          // FF*NC
    float* s_cy = s_cx + FF * NC;           // FF*NC
    float* s_ax = s_cy + FF * NC;           // FF*NC
    float* s_ay = s_ax + FF * NC;           // FF*NC

    const int bt = blockIdx.x;
    const int tid = threadIdx.x;

    // --- phase 1: load x tile ---
    {
        const float* br_ = binr + (size_t)bt * CHN * FF;
        const float* bi_ = bini + (size_t)bt * CHN * FF;
        for (int i = tid; i < CHN * FF; i += NTHR) {
            s_xr[i] = br_[i];
            s_xi[i] = bi_[i];
        }
    }
    __syncthreads();

    // --- phase 2: normalized covariance per bin ---
    for (int f = tid; f < FF; f += NTHR) {
        float xr[CHN], xi[CHN];
        float pw = 0.f;
#pragma unroll
        for (int c = 0; c < CHN; c++) {
            xr[c] = s_xr[c * FF + f];
            xi[c] = s_xi[c * FF + f];
            pw += xr[c] * xr[c] + xi[c] * xi[c];
        }
        float inv = 1.0f / fmaxf(pw, 1e-20f);
#pragma unroll
        for (int i = 0; i < CHN; i++)
#pragma unroll
            for (int j = 0; j < CHN; j++) {
                int c = i * 4 + j;
                s_cx[f * NC + c] = (xr[i] * xr[j] + xi[i] * xi[j]) * inv;
                s_cy[f * NC + c] = (xi[i] * xr[j] - xr[i] * xi[j]) * inv;
            }
    }
    __syncthreads();

    // --- phase 3: adj = |cov_f| * z/|z|, z = conj(cov_fm)*cov_fp ---
    for (int f = tid; f < FF; f += NTHR) {
        int fm = (f == 0) ? 0 : ((f == FF - 1) ? FF - 3 : f - 1);
        int fp = (f == 0) ? 2 : ((f == FF - 1) ? FF - 1 : f + 1);
#pragma unroll
        for (int c = 0; c < NC; c++) {
            float cx = s_cx[f * NC + c], cy = s_cy[f * NC + c];
            float ax, ay;
            if (c == 0 || c == 5 || c == 10 || c == 15) {
                ax = cx;
                ay = cy;
            } else {
                float a = s_cx[fm * NC + c], b = s_cy[fm * NC + c];
                float cc = s_cx[fp * NC + c], d = s_cy[fp * NC + c];
                float zr = a * cc + b * d;
                float zi = a * d - b * cc;
                float zl2 = zr * zr + zi * zi;
                float m = sqrtf(cx * cx + cy * cy);
                if (zl2 > 0.f) {
                    float s = m * rsqrtf(zl2);
                    ax = s * zr;
                    ay = s * zi;
                } else {
                    ax = m;
                    ay = 0.f;
                }
            }
            s_ax[f * NC + c] = ax;
            s_ay[f * NC + c] = ay;
        }
    }
    __syncthreads();

    // --- phase 4: bc[k][c] = sum_f adj[f][c] * band[f][k]  (FFMA2, 480 thr) ---
    const int NFG = 10;
    const int CHUNK = 49;  // 10*49 = 490 >= 481
    unsigned long long accX[8], accY[8];
#pragma unroll
    for (int p = 0; p < 8; p++) {
        accX[p] = 0ull;
        accY[p] = 0ull;
    }
    if (tid < NFG * KK) {
        const int fg = tid / KK, k = tid % KK;
        const int f0 = fg * CHUNK;
        const int f1 = (f0 + CHUNK < FF) ? f0 + CHUNK : FF;
        unsigned axbase = (unsigned)__cvta_generic_to_shared(s_ax);
        unsigned aybase = (unsigned)__cvta_generic_to_shared(s_ay);
        for (int f = f0; f < f1; f++) {
            float brv = bandr[f * KK + k];
            float biv = bandi[f * KK + k];
            unsigned long long brbr = pack2(brv, brv);
            unsigned long long bibi = pack2(biv, biv);
            unsigned long long nbnb = pack2(-biv, -biv);
            unsigned axa = axbase + f * NC * 4;
            unsigned aya = aybase + f * NC * 4;
#pragma unroll
            for (int p = 0; p < 8; p++) {
                unsigned long long AX = lds64(axa + p * 8);
                unsigned long long AY = lds64(aya + p * 8);
                accX[p] = fma2(AX, brbr, accX[p]);
                accX[p] = fma2(AY, nbnb, accX[p]);
                accY[p] = fma2(AX, bibi, accY[p]);
                accY[p] = fma2(AY, brbr, accY[p]);
            }
        }
    }
    __syncthreads();

    // --- partial reduction over the 10 f-chunks (reuse cov planes) ---
    if (tid < NFG * KK) {
        const int fg = tid / KK, k = tid % KK;
        float* px = s_cx + fg * (KK * NC) + k * NC;
        float* py = s_cy + fg * (KK * NC) + k * NC;
#pragma unroll
        for (int p = 0; p < 8; p++) {
            float lo, hi;
            unpack2(accX[p], lo, hi);
            px[2 * p] = lo;
            px[2 * p + 1] = hi;
            unpack2(accY[p], lo, hi);
            py[2 * p] = lo;
            py[2 * p + 1] = hi;
        }
    }
    __syncthreads();

    for (int s = tid; s < KK * NC; s += NTHR) {
        float sx = 0.f, sy = 0.f;
#pragma unroll
        for (int fg = 0; fg < NFG; fg++) {
            sx += s_cx[fg * (KK * NC) + s];
            sy += s_cy[fg * (KK * NC) + s];
        }
        s_xr[s] = sx;
        s_xi[s] = sy;
    }
    __syncthreads();

    // --- normalize by clipped diagonal sum, write to global ---
    for (int s = tid; s < KK * NC; s += NTHR) {
        int k = s >> 4;
        float ds = s_xr[k * NC + 0] + s_xr[k * NC + 5] + s_xr[k * NC + 10] +
                   s_xr[k * NC + 15];
        float inv = 1.0f / fmaxf(ds, 1e-20f);
        g_bc[(size_t)bt * (KK * NC) + s] = make_float2(s_xr[s] * inv, s_xi[s] * inv);
    }
}

// ---------------------------------------------------------------------------
// Kernel 2: parallel IIR scan, one warp per (b,k,c) chain, 32-frame segments
// ---------------------------------------------------------------------------
__global__ void __launch_bounds__(256) scan_kernel(const float* __restrict__ tau) {
    const int gw = (blockIdx.x * 256 + threadIdx.x) >> 5;  // chain id
    const int lane = threadIdx.x & 31;
    const int c = gw & 15;
    const int k = (gw >> 4) % KK;
    const int b = gw / (KK * NC);

    const float a = expf(-10.0f / tau[k]);
    const float om = 1.0f - a;

    const size_t stride = KK * NC;
    const size_t base = (size_t)b * TT * stride + (size_t)k * NC + c;
    const int SEG = TT / 32;  // 32
    const int t0 = lane * SEG;

    // --- pass A: local scan with zero carry-in; lane 0 applies y_0 = x_0 ---
    float2 y;
    {
        float2 x0 = g_bc[base + (size_t)t0 * stride];
        if (lane == 0) {
            y = x0;
        } else {
            y = make_float2(om * x0.x, om * x0.y);
        }
    }
#pragma unroll 8
    for (int j = 1; j < SEG; j++) {
        float2 x = g_bc[base + (size_t)(t0 + j) * stride];
        y.x = a * y.x + om * x.x;
        y.y = a * y.y + om * x.y;
    }

    // --- compose affine maps across lanes: Y_l = v_l + a^SEG * Y_{l-1} ---
    float w = a;
    w = w * w; w = w * w; w = w * w; w = w * w; w = w * w;  // a^32
    float vx = y.x, vy = y.y, ww = w;
#pragma unroll
    for (int d = 1; d < 32; d <<= 1) {
        float pvx = __shfl_up_sync(0xffffffffu, vx, d);
        float pvy = __shfl_up_sync(0xffffffffu, vy, d);
        float pw = __shfl_up_sync(0xffffffffu, ww, d);
        if (lane >= d) {
            vx += ww * pvx;
            vy += ww * pvy;
            ww *= pw;
        }
    }
    float cx_in = __shfl_up_sync(0xffffffffu, vx, 1);
    float cy_in = __shfl_up_sync(0xffffffffu, vy, 1);

    // --- pass B: replay with true carry-in, store ---
    {
        size_t idx = base + (size_t)t0 * stride;
        float2 x0 = g_bc[idx];
        if (lane == 0) {
            y = x0;
        } else {
            y.x = a * cx_in + om * x0.x;
            y.y = a * cy_in + om * x0.y;
        }
        g_bc[idx] = y;
    }
#pragma unroll 8
    for (int j = 1; j < SEG; j++) {
        size_t idx = base + (size_t)(t0 + j) * stride;
        float2 x = g_bc[idx];
        y.x = a * y.x + om * x.x;
        y.y = a * y.y + om * x.y;
        g_bc[idx] = y;
    }
}

// ---------------------------------------------------------------------------
// Kernel 3: pv[b,k,t,p] = Re( c2pv[p,:] . y[b,t,k,:] )
// ---------------------------------------------------------------------------
__global__ void __launch_bounds__(256) proj_kernel(const float* __restrict__ pr,
                                                   const float* __restrict__ pi,
                                                   float* __restrict__ out) {
    __shared__ float cr[256], ci[256];  // transposed: [c][p]
    int tid = threadIdx.x;
    {
        int c = tid >> 4, p = tid & 15;
        cr[c * 16 + p] = pr[p * 16 + c];
        ci[c * 16 + p] = pi[p * 16 + c];
    }
    __syncthreads();

    int g = blockIdx.x * 16 + (tid >> 4);  // flat (b,k,t) in output order
    int p = tid & 15;
    int t = g % TT;
    int bk = g / TT;
    int b = bk / KK, k = bk % KK;

    size_t ybase = (((size_t)b * TT + t) * KK + k) * NC;
    float s = 0.f;
#pragma unroll
    for (int c = 0; c < NC; c++) {
        float2 y = g_bc[ybase + c];
        s = fmaf(cr[c * 16 + p], y.x, s);
        s = fmaf(-ci[c * 16 + p], y.y, s);
    }
    out[(size_t)g * 16 + p] = s;
}

// ---------------------------------------------------------------------------
extern "C" void kernel_launch(void* const* d_in, const int* in_sizes, int n_in,
                              void* d_out, int out_size) {
    const float* binr = (const float*)d_in[0];
    const float* bini = (const float*)d_in[1];
    const float* bandr = (const float*)d_in[2];
    const float* bandi = (const float*)d_in[3];
    const float* pr = (const float*)d_in[4];
    const float* pi = (const float*)d_in[5];
    const float* tau = (const float*)d_in[6];
    float* out = (float*)d_out;

    const int smem = (2 * CHN * FF + 4 * FF * NC) * (int)sizeof(float);  // 138528 B
    cudaFuncSetAttribute(band_cov_kernel,
                         cudaFuncAttributeMaxDynamicSharedMemorySize, smem);

    band_cov_kernel<<<BB * TT, NTHR, smem>>>(binr, bini, bandr, bandi);
    scan_kernel<<<(BB * KK * NC * 32) / 256, 256>>>(tau);
    proj_kernel<<<BB * KK * TT / 16, 256>>>(pr, pi, out);
}

// round 8
// speedup vs baseline: 1.7723x; 1.3924x over previous
#include <cuda_runtime.h>

#define BB 4
#define TT 1024
#define CHN 4
#define FF 481
#define KK 48
#define NC 16
#define NTHR 512
#define NFG 10
#define CHUNK 49

// scratch: band-cov intermediate, (b,t,k,c) complex — scanned in place
__device__ float2 g_bc[BB * TT * KK * NC];  // 25.2 MB

__device__ __forceinline__ unsigned long long fma2(unsigned long long a,
                                                   unsigned long long b,
                                                   unsigned long long c) {
    unsigned long long d;
    asm("fma.rn.f32x2 %0, %1, %2, %3;" : "=l"(d) : "l"(a), "l"(b), "l"(c));
    return d;
}
__device__ __forceinline__ unsigned long long pack2(float lo, float hi) {
    unsigned long long r;
    asm("mov.b64 %0, {%1, %2};" : "=l"(r) : "f"(lo), "f"(hi));
    return r;
}
__device__ __forceinline__ void unpack2(unsigned long long v, float& lo, float& hi) {
    asm("mov.b64 {%0, %1}, %2;" : "=f"(lo), "=f"(hi) : "l"(v));
}
__device__ __forceinline__ void lds128(unsigned addr, unsigned long long& a,
                                       unsigned long long& b) {
    asm volatile("ld.shared.v2.u64 {%0, %1}, [%2];" : "=l"(a), "=l"(b) : "r"(addr));
}

// ---------------------------------------------------------------------------
// Kernel 1: per (b,t): cov -> phase-adjust -> band GEMM -> diag-normalize
// smem layout (floats):
//   s_x   [FF*8]      : per-bin channel data, float2 (re,im) x 4 ch, f-major
//   s_pw  [512]       : 1 / max(trace, 1e-20) per bin
//   s_ax  [FF*NC]     : adj real  (later reused: partial X, SoA by element)
//   s_ay  [FF*NC]     : adj imag  (later reused: partial Y)
// ---------------------------------------------------------------------------
__global__ void __launch_bounds__(NTHR, 1) band_cov_kernel(
    const float* __restrict__ binr, const float* __restrict__ bini,
    const float* __restrict__ bandr, const float* __restrict__ bandi) {
    extern __shared__ float sm[];
    float* s_x = sm;                 // FF*8 = 3848
    float* s_pw = s_x + FF * 8;      // 512
    float* s_ax = s_pw + 512;        // FF*NC = 7696
    float* s_ay = s_ax + FF * NC;    // 7696

    const int bt = blockIdx.x;
    const int tid = threadIdx.x;

    // --- phase 1: load x tile into f-major float2 layout ---
    {
        const float* br_ = binr + (size_t)bt * CHN * FF;
        const float* bi_ = bini + (size_t)bt * CHN * FF;
        for (int i = tid; i < CHN * FF; i += NTHR) {
            int ch = i / FF;
            int f = i - ch * FF;
            s_x[f * 8 + ch * 2] = br_[i];
            s_x[f * 8 + ch * 2 + 1] = bi_[i];
        }
    }
    __syncthreads();

    // --- phase 1b: inverse trace per bin ---
    for (int f = tid; f < FF; f += NTHR) {
        float pw = 0.f;
#pragma unroll
        for (int ch = 0; ch < CHN; ch++) {
            float r = s_x[f * 8 + 2 * ch];
            float m = s_x[f * 8 + 2 * ch + 1];
            pw += r * r + m * m;
        }
        s_pw[f] = 1.0f / fmaxf(pw, 1e-20f);
    }
    __syncthreads();

    // --- phase 2+3 fused: adj[f][c] directly (uniform formula, no branch) ---
    {
        const float2* x2 = (const float2*)s_x;  // x2[f*4 + ch]
        for (int idx = tid; idx < FF * NC; idx += NTHR) {
            int f = idx >> 4;
            int c = idx & 15;
            int i = c >> 2, j = c & 3;
            int fm = (f == 0) ? 0 : ((f == FF - 1) ? FF - 3 : f - 1);
            int fp = (f == 0) ? 2 : ((f == FF - 1) ? FF - 1 : f + 1);

            float2 aF = x2[f * 4 + i], bF = x2[f * 4 + j];
            float2 aM = x2[fm * 4 + i], bM = x2[fm * 4 + j];
            float2 aP = x2[fp * 4 + i], bP = x2[fp * 4 + j];

            // cov = x_i * conj(x_j) (raw)
            float crF = aF.x * bF.x + aF.y * bF.y;
            float ciF = aF.y * bF.x - aF.x * bF.y;
            float crM = aM.x * bM.x + aM.y * bM.y;
            float ciM = aM.y * bM.x - aM.x * bM.y;
            float crP = aP.x * bP.x + aP.y * bP.y;
            float ciP = aP.y * bP.x - aP.x * bP.y;

            // z = conj(cov_m) * cov_p  (angle invariant to +scaling)
            float zr = crM * crP + ciM * ciP;
            float zi = crM * ciP - ciM * crP;
            float zl2 = zr * zr + zi * zi;

            // m = |normalized cov at f|
            float m = sqrtf(crF * crF + ciF * ciF) * s_pw[f];

            float ax, ay;
            if (zl2 > 0.f) {
                float s = m * rsqrtf(zl2);
                ax = s * zr;
                ay = s * zi;
            } else {
                ax = m;
                ay = 0.f;
            }
            s_ax[idx] = ax;
            s_ay[idx] = ay;
        }
    }
    __syncthreads();

    // --- phase 4: bc[k][c] = sum_f adj[f][c] * band[f][k]  (FFMA2 + LDS.128) ---
    unsigned long long accX[8], accY[8];
#pragma unroll
    for (int p = 0; p < 8; p++) {
        accX[p] = 0ull;
        accY[p] = 0ull;
    }
    const bool act = tid < NFG * KK;
    if (act) {
        const int fg = tid / KK, k = tid - (tid / KK) * KK;
        const int f0 = fg * CHUNK;
        const int f1 = (f0 + CHUNK < FF) ? f0 + CHUNK : FF;
        unsigned axbase = (unsigned)__cvta_generic_to_shared(s_ax);
        unsigned aybase = (unsigned)__cvta_generic_to_shared(s_ay);
        float brn = bandr[f0 * KK + k];
        float bin_ = bandi[f0 * KK + k];
        for (int f = f0; f < f1; f++) {
            float brv = brn, biv = bin_;
            if (f + 1 < f1) {  // prefetch next band coefficient
                brn = bandr[(f + 1) * KK + k];
                bin_ = bandi[(f + 1) * KK + k];
            }
            unsigned long long brbr = pack2(brv, brv);
            unsigned long long bibi = pack2(biv, biv);
            unsigned long long nbnb = pack2(-biv, -biv);
            unsigned axa = axbase + f * 64;
            unsigned aya = aybase + f * 64;
#pragma unroll
            for (int q = 0; q < 4; q++) {
                unsigned long long ax0, ax1, ay0, ay1;
                lds128(axa + q * 16, ax0, ax1);
                lds128(aya + q * 16, ay0, ay1);
                int p = 2 * q;
                accX[p] = fma2(ax0, brbr, accX[p]);
                accX[p] = fma2(ay0, nbnb, accX[p]);
                accY[p] = fma2(ax0, bibi, accY[p]);
                accY[p] = fma2(ay0, brbr, accY[p]);
                accX[p + 1] = fma2(ax1, brbr, accX[p + 1]);
                accX[p + 1] = fma2(ay1, nbnb, accX[p + 1]);
                accY[p + 1] = fma2(ax1, bibi, accY[p + 1]);
                accY[p + 1] = fma2(ay1, brbr, accY[p + 1]);
            }
        }
    }
    __syncthreads();  // all adj reads complete; planes now reusable

    // --- partial store, SoA: part[e][thread] with thread = fg*48+k ---
    if (act) {
#pragma unroll
        for (int p = 0; p < 8; p++) {
            float lo, hi;
            unpack2(accX[p], lo, hi);
            s_ax[(2 * p) * (NFG * KK) + tid] = lo;
            s_ax[(2 * p + 1) * (NFG * KK) + tid] = hi;
            unpack2(accY[p], lo, hi);
            s_ay[(2 * p) * (NFG * KK) + tid] = lo;
            s_ay[(2 * p + 1) * (NFG * KK) + tid] = hi;
        }
    }
    __syncthreads();

    // --- reduce over fg, stage SoA: stage[e*48+k] ---
    for (int r = tid; r < KK * NC; r += NTHR) {
        int e = r / KK;
        int k = r - e * KK;
        float sx = 0.f, sy = 0.f;
#pragma unroll
        for (int fg = 0; fg < NFG; fg++) {
            sx += s_ax[e * (NFG * KK) + fg * KK + k];
            sy += s_ay[e * (NFG * KK) + fg * KK + k];
        }
        s_x[e * KK + k] = sx;
        s_x[KK * NC + e * KK + k] = sy;
    }
    __syncthreads();

    // --- normalize by clipped diagonal sum, write (b,t,k,c) ---
    for (int r = tid; r < KK * NC; r += NTHR) {
        int c = r / KK;
        int k = r - c * KK;
        float ds = s_x[0 * KK + k] + s_x[5 * KK + k] + s_x[10 * KK + k] +
                   s_x[15 * KK + k];
        float inv = 1.0f / fmaxf(ds, 1e-20f);
        g_bc[(size_t)bt * (KK * NC) + k * NC + c] =
            make_float2(s_x[c * KK + k] * inv, s_x[KK * NC + c * KK + k] * inv);
    }
}

// ---------------------------------------------------------------------------
// Kernel 2: parallel IIR scan, one warp per (b,k,c) chain, 32-frame segments
// ---------------------------------------------------------------------------
__global__ void __launch_bounds__(256) scan_kernel(const float* __restrict__ tau) {
    const int gw = (blockIdx.x * 256 + threadIdx.x) >> 5;  // chain id
    const int lane = threadIdx.x & 31;
    const int c = gw & 15;
    const int k = (gw >> 4) % KK;
    const int b = gw / (KK * NC);

    const float a = expf(-10.0f / tau[k]);
    const float om = 1.0f - a;

    const size_t stride = KK * NC;
    const size_t base = (size_t)b * TT * stride + (size_t)k * NC + c;
    const int SEG = TT / 32;  // 32
    const int t0 = lane * SEG;

    // --- pass A: local scan with zero carry-in; lane 0 applies y_0 = x_0 ---
    float2 y;
    {
        float2 x0 = g_bc[base + (size_t)t0 * stride];
        if (lane == 0) {
            y = x0;
        } else {
            y = make_float2(om * x0.x, om * x0.y);
        }
    }
#pragma unroll 8
    for (int j = 1; j < SEG; j++) {
        float2 x = g_bc[base + (size_t)(t0 + j) * stride];
        y.x = a * y.x + om * x.x;
        y.y = a * y.y + om * x.y;
    }

    // --- compose affine maps across lanes: Y_l = v_l + a^SEG * Y_{l-1} ---
    float w = a;
    w = w * w; w = w * w; w = w * w; w = w * w; w = w * w;  // a^32
    float vx = y.x, vy = y.y, ww = w;
#pragma unroll
    for (int d = 1; d < 32; d <<= 1) {
        float pvx = __shfl_up_sync(0xffffffffu, vx, d);
        float pvy = __shfl_up_sync(0xffffffffu, vy, d);
        float pw = __shfl_up_sync(0xffffffffu, ww, d);
        if (lane >= d) {
            vx += ww * pvx;
            vy += ww * pvy;
            ww *= pw;
        }
    }
    float cx_in = __shfl_up_sync(0xffffffffu, vx, 1);
    float cy_in = __shfl_up_sync(0xffffffffu, vy, 1);

    // --- pass B: replay with true carry-in, store ---
    {
        size_t idx = base + (size_t)t0 * stride;
        float2 x0 = g_bc[idx];
        if (lane == 0) {
            y = x0;
        } else {
            y.x = a * cx_in + om * x0.x;
            y.y = a * cy_in + om * x0.y;
        }
        g_bc[idx] = y;
    }
#pragma unroll 8
    for (int j = 1; j < SEG; j++) {
        size_t idx = base + (size_t)(t0 + j) * stride;
        float2 x = g_bc[idx];
        y.x = a * y.x + om * x.x;
        y.y = a * y.y + om * x.y;
        g_bc[idx] = y;
    }
}

// ---------------------------------------------------------------------------
// Kernel 3: pv[b,k,t,p] = Re( c2pv[p,:] . y[b,t,k,:] )
// ---------------------------------------------------------------------------
__global__ void __launch_bounds__(256) proj_kernel(const float* __restrict__ pr,
                                                   const float* __restrict__ pi,
                                                   float* __restrict__ out) {
    __shared__ float cr[256], ci[256];  // transposed: [c][p]
    int tid = threadIdx.x;
    {
        int c = tid >> 4, p = tid & 15;
        cr[c * 16 + p] = pr[p * 16 + c];
        ci[c * 16 + p] = pi[p * 16 + c];
    }
    __syncthreads();

    int g = blockIdx.x * 16 + (tid >> 4);  // flat (b,k,t) in output order
    int p = tid & 15;
    int t = g % TT;
    int bk = g / TT;
    int b = bk / KK, k = bk % KK;

    size_t ybase = (((size_t)b * TT + t) * KK + k) * NC;
    float s = 0.f;
#pragma unroll
    for (int c = 0; c < NC; c++) {
        float2 y = g_bc[ybase + c];
        s = fmaf(cr[c * 16 + p], y.x, s);
        s = fmaf(-ci[c * 16 + p], y.y, s);
    }
    out[(size_t)g * 16 + p] = s;
}

// ---------------------------------------------------------------------------
extern "C" void kernel_launch(void* const* d_in, const int* in_sizes, int n_in,
                              void* d_out, int out_size) {
    const float* binr = (const float*)d_in[0];
    const float* bini = (const float*)d_in[1];
    const float* bandr = (const float*)d_in[2];
    const float* bandi = (const float*)d_in[3];
    const float* pr = (const float*)d_in[4];
    const float* pi = (const float*)d_in[5];
    const float* tau = (const float*)d_in[6];
    float* out = (float*)d_out;

    const int smem = (FF * 8 + 512 + 2 * FF * NC) * (int)sizeof(float);  // 79008 B
    cudaFuncSetAttribute(band_cov_kernel,
                         cudaFuncAttributeMaxDynamicSharedMemorySize, smem);

    band_cov_kernel<<<BB * TT, NTHR, smem>>>(binr, bini, bandr, bandi);
    scan_kernel<<<(BB * KK * NC * 32) / 256, 256>>>(tau);
    proj_kernel<<<BB * KK * TT / 16, 256>>>(pr, pi, out);
}